// round 11
// baseline (speedup 1.0000x reference)
#include <cuda_runtime.h>
#include <cuda_bf16.h>
#include <cuda_fp16.h>
#include <mma.h>
#include <cstdint>

using namespace nvcuda;

#define N_NODES 100000
#define N_EDGES 3200000
#define N_GRAPHS 512
#define IN_DIM 29
#define K1PAD 32
#define HID 128
#define LAT 256
#define NB_SCAN ((N_NODES + 255) / 256)   // 391

// ---------------- scratch (static device globals; no allocation) -----------
__device__ __half g_hw16[(size_t)N_NODES * HID];  // gemm output (pre-bias)
__device__ __half g_h16A[(size_t)N_NODES * HID];  // relu'd layer act ping
__device__ __half g_h16B[(size_t)N_NODES * HID];  // relu'd layer act pong
__device__ __half g_x16[(size_t)N_NODES * K1PAD]; // fp16 x, padded to 32
__device__ __half g_z16[(size_t)N_NODES * K1PAD]; // aggregated x (fp16)
__device__ __half g_W1h[K1PAD * HID];             // padded fp16 W1
__device__ __half g_W2h[HID * HID];
__device__ __half g_W3h[HID * HID];
__device__ float g_dis[N_NODES];                  // deg^-1/2 (with self loop)
__device__ int   g_deg[N_NODES];
__device__ int   g_scan[N_NODES];
__device__ int   g_bsum[NB_SCAN];
__device__ int   g_boff[NB_SCAN];
__device__ int   g_rowstart[N_NODES + 1];         // CSR row offsets (by dst)
__device__ int   g_cursor[N_NODES];
__device__ int   g_csri[N_EDGES];                 // src only (4B)
__device__ float g_pool[N_GRAPHS * HID];
__device__ float g_cnt[N_GRAPHS];

// ---------------- init: zero per-launch accumulators -----------------------
__global__ void init_kernel() {
    int i = blockIdx.x * blockDim.x + threadIdx.x;
    if (i < N_NODES) g_deg[i] = 0;
    if (i < N_GRAPHS * HID) g_pool[i] = 0.f;
    if (i < N_GRAPHS) g_cnt[i] = 0.f;
}

// ---------------- convert x and weights to fp16 -----------------------------
__global__ void xconv_kernel(const float* __restrict__ x) {
    int i = blockIdx.x * blockDim.x + threadIdx.x;
    if (i >= N_NODES * K1PAD) return;
    int n = i >> 5;          // / 32
    int c = i & 31;
    g_x16[i] = (c < IN_DIM) ? __float2half(x[(size_t)n * IN_DIM + c]) : __half(0.f);
}

__global__ void wconv_kernel(const float* __restrict__ W1,
                             const float* __restrict__ W2,
                             const float* __restrict__ W3) {
    int i = blockIdx.x * blockDim.x + threadIdx.x;
    if (i < HID * HID) {
        g_W2h[i] = __float2half(W2[i]);
        g_W3h[i] = __float2half(W3[i]);
    }
    if (i < K1PAD * HID) {
        int k = i >> 7;      // / HID
        g_W1h[i] = (k < IN_DIM) ? __float2half(W1[i]) : __half(0.f);
    }
}

// ---------------- edge prep ------------------------------------------------
__global__ void edge_count_kernel(const int* __restrict__ ei) {
    int e = blockIdx.x * blockDim.x + threadIdx.x;
    if (e >= N_EDGES) return;
    atomicAdd(&g_deg[ei[N_EDGES + e]], 1);
}

// ---------------- CSR build: 3-pass scan + fill (dis fused into scanA) ------
__global__ void scanA_kernel() {
    __shared__ int s[256];
    int tid = threadIdx.x;
    int i = blockIdx.x * 256 + tid;
    int v = (i < N_NODES) ? g_deg[i] : 0;
    if (i < N_NODES) g_dis[i] = rsqrtf((float)(v + 1));
    s[tid] = v;
    __syncthreads();
#pragma unroll
    for (int off = 1; off < 256; off <<= 1) {
        int t = (tid >= off) ? s[tid - off] : 0;
        __syncthreads();
        s[tid] += t;
        __syncthreads();
    }
    if (i < N_NODES) g_scan[i] = s[tid] - v;
    if (tid == 255) g_bsum[blockIdx.x] = s[255];
}

__global__ void scanB_kernel() {      // single block, 512 threads
    __shared__ int s[512];
    int tid = threadIdx.x;
    int v = (tid < NB_SCAN) ? g_bsum[tid] : 0;
    s[tid] = v;
    __syncthreads();
#pragma unroll
    for (int off = 1; off < 512; off <<= 1) {
        int t = (tid >= off) ? s[tid - off] : 0;
        __syncthreads();
        s[tid] += t;
        __syncthreads();
    }
    if (tid < NB_SCAN) g_boff[tid] = s[tid] - v;
}

__global__ void scanC_kernel() {
    int i = blockIdx.x * 256 + threadIdx.x;
    if (i < N_NODES) {
        int r = g_scan[i] + g_boff[blockIdx.x];
        g_rowstart[i] = r;
        g_cursor[i] = r;
    }
    if (i == 0) g_rowstart[N_NODES] = N_EDGES;
}

__global__ void csr_fill_kernel(const int* __restrict__ ei) {
    int e = blockIdx.x * blockDim.x + threadIdx.x;
    if (e >= N_EDGES) return;
    int s = ei[e];
    int d = ei[N_EDGES + e];
    int pos = atomicAdd(&g_cursor[d], 1);
    g_csri[pos] = s;
}

// ---------------- layer-1 agg: z16[n] = sum_in x16[src]*w + x16[n]*d2 -------
// one warp per destination node; lanes 0..15 hold the 32-col fp16 row (4B each)
__global__ __launch_bounds__(256)
void agg_x16_kernel() {
    int warp = threadIdx.x >> 5;
    int lane = threadIdx.x & 31;
    int n = blockIdx.x * 8 + warp;
    if (n >= N_NODES) return;

    int p0 = g_rowstart[n];
    int p1 = g_rowstart[n + 1];
    float d = g_dis[n];
    float d2 = d * d;

    unsigned hv = (lane < 16)
        ? __ldg((const unsigned*)(g_x16 + (size_t)n * K1PAD) + lane) : 0u;
    float2 h = __half22float2(*reinterpret_cast<__half2*>(&hv));
    float2 acc = make_float2(h.x * d2, h.y * d2);

#pragma unroll 4
    for (int p = p0; p < p1; p++) {
        int s = __ldg(g_csri + p);
        float w = __ldg(g_dis + s) * d;
        unsigned v = (lane < 16)
            ? __ldg((const unsigned*)(g_x16 + (size_t)s * K1PAD) + lane) : 0u;
        float2 f = __half22float2(*reinterpret_cast<__half2*>(&v));
        acc.x += f.x * w;
        acc.y += f.y * w;
    }
    if (lane < 16) {
        __half2 o = __floats2half2_rn(acc.x, acc.y);
        ((unsigned*)(g_z16 + (size_t)n * K1PAD))[lane] =
            *reinterpret_cast<unsigned*>(&o);
    }
}

// ---------------- layer-1 tc GEMM: h16A = relu(z16 @ W1h + b1), K=32 --------
#define TCBM 64
__global__ __launch_bounds__(256, 2)
void gemm1_tc_kernel(const float* __restrict__ b) {
    __shared__ alignas(16) __half As[TCBM * K1PAD];   // 4 KB
    __shared__ alignas(16) __half Ws[K1PAD * HID];    // 8 KB
    __shared__ alignas(16) float stage[8 * 256];      // 8 KB

    int tid = threadIdx.x;
    int wid = tid >> 5;
    int lane = tid & 31;
    int rs = wid >> 1;
    int cs = wid & 1;
    int row0 = blockIdx.x * TCBM;

    for (int i = tid; i < TCBM * 4; i += 256) {       // 64 rows x 4 uint4 (32 halves)
        int r = i >> 2;
        int c = i & 3;
        uint4 v = make_uint4(0u, 0u, 0u, 0u);
        int row = row0 + r;
        if (row < N_NODES)
            v = *reinterpret_cast<const uint4*>(g_z16 + (size_t)row * K1PAD + c * 8);
        *reinterpret_cast<uint4*>(As + r * K1PAD + c * 8) = v;
    }
    for (int i = tid; i < K1PAD * 16; i += 256) {
        int r = i >> 4;
        int c = i & 15;
        *reinterpret_cast<uint4*>(Ws + r * HID + c * 8) =
            *reinterpret_cast<const uint4*>(g_W1h + r * HID + c * 8);
    }
    __syncthreads();

    wmma::fragment<wmma::accumulator, 16, 16, 16, float> acc[4];
#pragma unroll
    for (int j = 0; j < 4; j++) wmma::fill_fragment(acc[j], 0.f);

#pragma unroll
    for (int k = 0; k < 2; k++) {
        wmma::fragment<wmma::matrix_a, 16, 16, 16, __half, wmma::row_major> af;
        wmma::load_matrix_sync(af, As + (rs * 16) * K1PAD + k * 16, K1PAD);
#pragma unroll
        for (int j = 0; j < 4; j++) {
            wmma::fragment<wmma::matrix_b, 16, 16, 16, __half, wmma::row_major> bf;
            wmma::load_matrix_sync(bf, Ws + (k * 16) * HID + cs * 64 + j * 16, HID);
            wmma::mma_sync(acc[j], af, bf, acc[j]);
        }
    }

    float* st = stage + wid * 256;
#pragma unroll
    for (int j = 0; j < 4; j++) {
        wmma::store_matrix_sync(st, acc[j], 16, wmma::mem_row_major);
        __syncwarp();
        int r = lane >> 1;
        int c0 = (lane & 1) * 8;
        int row = row0 + rs * 16 + r;
        if (row < N_NODES) {
            int col = cs * 64 + j * 16 + c0;
            float* sp = st + r * 16 + c0;
            float v[8];
#pragma unroll
            for (int q = 0; q < 8; q++) v[q] = fmaxf(sp[q] + __ldg(b + col + q), 0.f);
            __half2 h0 = __floats2half2_rn(v[0], v[1]);
            __half2 h1 = __floats2half2_rn(v[2], v[3]);
            __half2 h2 = __floats2half2_rn(v[4], v[5]);
            __half2 h3 = __floats2half2_rn(v[6], v[7]);
            uint4 u;
            u.x = *reinterpret_cast<unsigned*>(&h0);
            u.y = *reinterpret_cast<unsigned*>(&h1);
            u.z = *reinterpret_cast<unsigned*>(&h2);
            u.w = *reinterpret_cast<unsigned*>(&h3);
            *reinterpret_cast<uint4*>(g_h16A + (size_t)row * HID + col) = u;
        }
        __syncwarp();
    }
}

// ---------------- tensor-core GEMM (layers 2/3): g_hw16 = A16 @ W16 ---------
__global__ __launch_bounds__(256, 2)
void gemm_tc_kernel(const __half* __restrict__ A, const __half* __restrict__ W) {
    __shared__ alignas(16) __half As[TCBM * HID];   // 16 KB
    __shared__ alignas(16) __half Ws[64 * HID];     // 16 KB (reused as stage)

    int tid = threadIdx.x;
    int wid = tid >> 5;
    int lane = tid & 31;
    int rs = wid >> 1;
    int cs = wid & 1;
    int row0 = blockIdx.x * TCBM;

    for (int i = tid; i < TCBM * 16; i += 256) {
        int r = i >> 4;
        int c = i & 15;
        uint4 v = make_uint4(0u, 0u, 0u, 0u);
        int row = row0 + r;
        if (row < N_NODES)
            v = *reinterpret_cast<const uint4*>(A + (size_t)row * HID + c * 8);
        *reinterpret_cast<uint4*>(As + r * HID + c * 8) = v;
    }

    wmma::fragment<wmma::accumulator, 16, 16, 16, float> acc[4];
#pragma unroll
    for (int j = 0; j < 4; j++) wmma::fill_fragment(acc[j], 0.f);

#pragma unroll
    for (int ch = 0; ch < 2; ch++) {
        __syncthreads();
        for (int i = tid; i < 64 * 16; i += 256) {
            int r = i >> 4;
            int c = i & 15;
            *reinterpret_cast<uint4*>(Ws + r * HID + c * 8) =
                *reinterpret_cast<const uint4*>(W + (size_t)(ch * 64 + r) * HID + c * 8);
        }
        __syncthreads();
#pragma unroll
        for (int k = 0; k < 4; k++) {
            wmma::fragment<wmma::matrix_a, 16, 16, 16, __half, wmma::row_major> af;
            wmma::load_matrix_sync(af, As + (rs * 16) * HID + ch * 64 + k * 16, HID);
#pragma unroll
            for (int j = 0; j < 4; j++) {
                wmma::fragment<wmma::matrix_b, 16, 16, 16, __half, wmma::row_major> bf;
                wmma::load_matrix_sync(bf, Ws + (k * 16) * HID + cs * 64 + j * 16, HID);
                wmma::mma_sync(acc[j], af, bf, acc[j]);
            }
        }
    }
    __syncthreads();            // all mma done; Ws free for staging

    float* stage = reinterpret_cast<float*>(Ws) + wid * 256;
#pragma unroll
    for (int j = 0; j < 4; j++) {
        wmma::store_matrix_sync(stage, acc[j], 16, wmma::mem_row_major);
        __syncwarp();
        int r = lane >> 1;
        int c0 = (lane & 1) * 8;
        int row = row0 + rs * 16 + r;
        if (row < N_NODES) {
            float* sp = stage + r * 16 + c0;
            __half2 h0 = __floats2half2_rn(sp[0], sp[1]);
            __half2 h1 = __floats2half2_rn(sp[2], sp[3]);
            __half2 h2 = __floats2half2_rn(sp[4], sp[5]);
            __half2 h3 = __floats2half2_rn(sp[6], sp[7]);
            uint4 u;
            u.x = *reinterpret_cast<unsigned*>(&h0);
            u.y = *reinterpret_cast<unsigned*>(&h1);
            u.z = *reinterpret_cast<unsigned*>(&h2);
            u.w = *reinterpret_cast<unsigned*>(&h3);
            *reinterpret_cast<uint4*>(g_hw16 + (size_t)row * HID + cs * 64 + j * 16 + c0) = u;
        }
        __syncwarp();
    }
}

// ---------------- CSR agg: out16 = relu( sum hw16[src]*w + hw16[n]*d2 + b ) -
__global__ __launch_bounds__(256)
void agg_h16_kernel(const float* __restrict__ b, __half* __restrict__ out) {
    int warp = threadIdx.x >> 5;
    int lane = threadIdx.x & 31;
    int n = blockIdx.x * 8 + warp;
    if (n >= N_NODES) return;

    int p0 = g_rowstart[n];
    int p1 = g_rowstart[n + 1];

    float d = g_dis[n];
    float d2 = d * d;
    uint2 hr = __ldg((const uint2*)(g_hw16 + (size_t)n * HID) + lane);
    float2 h01 = __half22float2(*reinterpret_cast<__half2*>(&hr.x));
    float2 h23 = __half22float2(*reinterpret_cast<__half2*>(&hr.y));
    float4 bv = __ldg((const float4*)b + lane);
    float4 a = make_float4(h01.x * d2 + bv.x, h01.y * d2 + bv.y,
                           h23.x * d2 + bv.z, h23.y * d2 + bv.w);

#pragma unroll 4
    for (int p = p0; p < p1; p++) {
        int s = __ldg(g_csri + p);
        float w = __ldg(g_dis + s) * d;
        uint2 vr = __ldg((const uint2*)(g_hw16 + (size_t)s * HID) + lane);
        float2 v01 = __half22float2(*reinterpret_cast<__half2*>(&vr.x));
        float2 v23 = __half22float2(*reinterpret_cast<__half2*>(&vr.y));
        a.x += v01.x * w;
        a.y += v01.y * w;
        a.z += v23.x * w;
        a.w += v23.y * w;
    }
    a.x = fmaxf(a.x, 0.f);
    a.y = fmaxf(a.y, 0.f);
    a.z = fmaxf(a.z, 0.f);
    a.w = fmaxf(a.w, 0.f);
    __half2 o0 = __floats2half2_rn(a.x, a.y);
    __half2 o1 = __floats2half2_rn(a.z, a.w);
    uint2 u;
    u.x = *reinterpret_cast<unsigned*>(&o0);
    u.y = *reinterpret_cast<unsigned*>(&o1);
    ((uint2*)(out + (size_t)n * HID))[lane] = u;
}

// ---------------- pooling (input already relu'd fp16) ------------------------
__global__ __launch_bounds__(128)
void pool_kernel(const __half* __restrict__ h, const int* __restrict__ batch) {
    int c = threadIdx.x;
    int n0 = blockIdx.x * 128;
    int nend = min(n0 + 128, N_NODES);
    if (n0 >= nend) return;
    int curg = batch[n0];
    float run = 0.f;
    int rl = 0;
    for (int n = n0; n < nend; n++) {
        int g = batch[n];
        if (g != curg) {
            atomicAdd(&g_pool[curg * HID + c], run);
            if (c == 0) atomicAdd(&g_cnt[curg], (float)rl);
            run = 0.f; rl = 0; curg = g;
        }
        run += __half2float(h[(size_t)n * HID + c]);
        rl++;
    }
    atomicAdd(&g_pool[curg * HID + c], run);
    if (c == 0) atomicAdd(&g_cnt[curg], (float)rl);
}

// ---------------- heads -----------------------------------------------------
__global__ __launch_bounds__(256)
void head_kernel(const float* __restrict__ Wmu, const float* __restrict__ bmu,
                 const float* __restrict__ Wlv, const float* __restrict__ blv,
                 float* __restrict__ out) {
    __shared__ float p[HID];
    int g = blockIdx.x;
    int j = threadIdx.x;
    if (j < HID) {
        float c = fmaxf(g_cnt[g], 1.f);
        p[j] = g_pool[g * HID + j] / c;
    }
    __syncthreads();
    float smu = bmu[j];
    float slv = blv[j];
#pragma unroll 4
    for (int k = 0; k < HID; k++) {
        float pk = p[k];
        smu += pk * Wmu[k * LAT + j];
        slv += pk * Wlv[k * LAT + j];
    }
    out[(size_t)g * LAT + j] = smu;
    out[(size_t)N_GRAPHS * LAT + (size_t)g * LAT + j] = slv;
}

// ---------------- launch ----------------------------------------------------
extern "C" void kernel_launch(void* const* d_in, const int* in_sizes, int n_in,
                              void* d_out, int out_size) {
    const float* x     = (const float*)d_in[0];
    const int*   ei    = (const int*)d_in[1];
    const int*   batch = (const int*)d_in[2];
    const float* W1  = (const float*)d_in[3];
    const float* b1  = (const float*)d_in[4];
    const float* W2  = (const float*)d_in[5];
    const float* b2  = (const float*)d_in[6];
    const float* W3  = (const float*)d_in[7];
    const float* b3  = (const float*)d_in[8];
    const float* Wmu = (const float*)d_in[9];
    const float* bmu = (const float*)d_in[10];
    const float* Wlv = (const float*)d_in[11];
    const float* blv = (const float*)d_in[12];
    float* out = (float*)d_out;

    __half *pA16, *pB16, *pW2h, *pW3h;
    cudaGetSymbolAddress((void**)&pA16, g_h16A);
    cudaGetSymbolAddress((void**)&pB16, g_h16B);
    cudaGetSymbolAddress((void**)&pW2h, g_W2h);
    cudaGetSymbolAddress((void**)&pW3h, g_W3h);

    int nb_nodes = (N_NODES + 255) / 256;
    int nb_edges = (N_EDGES + 255) / 256;

    init_kernel<<<nb_nodes, 256>>>();
    xconv_kernel<<<(N_NODES * K1PAD + 255) / 256, 256>>>(x);
    wconv_kernel<<<(HID * HID + 255) / 256, 256>>>(W1, W2, W3);
    edge_count_kernel<<<nb_edges, 256>>>(ei);
    scanA_kernel<<<NB_SCAN, 256>>>();
    scanB_kernel<<<1, 512>>>();
    scanC_kernel<<<NB_SCAN, 256>>>();
    csr_fill_kernel<<<nb_edges, 256>>>(ei);

    int nb_gtc = (N_NODES + TCBM - 1) / TCBM;
    int nb_agg = (N_NODES + 7) / 8;

    // layer 1 (reordered): z16 = agg(x16) ; h16A = relu(z16 @ W1 + b1)
    agg_x16_kernel<<<nb_agg, 256>>>();
    gemm1_tc_kernel<<<nb_gtc, 256>>>(b1);
    // layer 2: hw16 = h16A @ W2 ; h16B = relu(agg(hw16) + b2)
    gemm_tc_kernel<<<nb_gtc, 256>>>(pA16, pW2h);
    agg_h16_kernel<<<nb_agg, 256>>>(b2, pB16);
    // layer 3: hw16 = h16B @ W3 ; h16A = relu(agg(hw16) + b3)
    gemm_tc_kernel<<<nb_gtc, 256>>>(pB16, pW3h);
    agg_h16_kernel<<<nb_agg, 256>>>(b3, pA16);

    pool_kernel<<<(N_NODES + 127) / 128, 128>>>(pA16, batch);
    head_kernel<<<N_GRAPHS, 256>>>(Wmu, bmu, Wlv, blv, out);
}

// round 12
// speedup vs baseline: 1.0360x; 1.0360x over previous
#include <cuda_runtime.h>
#include <cuda_bf16.h>
#include <cuda_fp16.h>
#include <mma.h>
#include <cstdint>

using namespace nvcuda;

#define N_NODES 100000
#define N_EDGES 3200000
#define N_GRAPHS 512
#define IN_DIM 29
#define K1PAD 32
#define HID 128
#define LAT 256
#define NB_SCAN ((N_NODES + 255) / 256)   // 391

// ---------------- scratch (static device globals; no allocation) -----------
__device__ __half g_hw16[(size_t)N_NODES * HID];  // gemm output (pre-bias)
__device__ __half g_h16A[(size_t)N_NODES * HID];  // relu'd layer act ping
__device__ __half g_h16B[(size_t)N_NODES * HID];  // relu'd layer act pong
__device__ __half g_x16[(size_t)N_NODES * K1PAD]; // fp16 x, padded to 32
__device__ __half g_z16[(size_t)N_NODES * K1PAD]; // aggregated x (fp16)
__device__ __half g_W1h[K1PAD * HID];             // padded fp16 W1
__device__ __half g_W2h[HID * HID];
__device__ __half g_W3h[HID * HID];
__device__ float g_dis[N_NODES];                  // deg^-1/2 (with self loop)
__device__ int   g_deg[N_NODES];
__device__ int   g_scan[N_NODES];
__device__ int   g_bsum[NB_SCAN];
__device__ int   g_boff[NB_SCAN];
__device__ int   g_rowstart[N_NODES + 1];         // CSR row offsets (by dst)
__device__ int   g_cursor[N_NODES];
__device__ int2  g_csr[N_EDGES];                  // (src, bitcast(weight))
__device__ float g_pool[N_GRAPHS * HID];
__device__ float g_cnt[N_GRAPHS];

// ---------------- fused prep: zero accumulators + fp16 conversions ----------
// grid covers N_NODES*32 elements (xconv); other roles strided inside.
__global__ void prep_kernel(const float* __restrict__ x,
                            const float* __restrict__ W1,
                            const float* __restrict__ W2,
                            const float* __restrict__ W3) {
    int i = blockIdx.x * blockDim.x + threadIdx.x;
    if (i < N_NODES * K1PAD) {
        int n = i >> 5;
        int c = i & 31;
        g_x16[i] = (c < IN_DIM) ? __float2half(x[(size_t)n * IN_DIM + c]) : __half(0.f);
    }
    if (i < N_NODES) g_deg[i] = 0;
    if (i < N_GRAPHS * HID) g_pool[i] = 0.f;
    if (i < N_GRAPHS) g_cnt[i] = 0.f;
    if (i < HID * HID) {
        g_W2h[i] = __float2half(W2[i]);
        g_W3h[i] = __float2half(W3[i]);
    }
    if (i < K1PAD * HID) {
        int k = i >> 7;
        g_W1h[i] = (k < IN_DIM) ? __float2half(W1[i]) : __half(0.f);
    }
}

// ---------------- edge prep ------------------------------------------------
__global__ void edge_count_kernel(const int* __restrict__ ei) {
    int e = blockIdx.x * blockDim.x + threadIdx.x;
    if (e >= N_EDGES) return;
    atomicAdd(&g_deg[ei[N_EDGES + e]], 1);
}

// ---------------- CSR build: 3-pass scan + fill (dis fused into scanA) ------
__global__ void scanA_kernel() {
    __shared__ int s[256];
    int tid = threadIdx.x;
    int i = blockIdx.x * 256 + tid;
    int v = (i < N_NODES) ? g_deg[i] : 0;
    if (i < N_NODES) g_dis[i] = rsqrtf((float)(v + 1));
    s[tid] = v;
    __syncthreads();
#pragma unroll
    for (int off = 1; off < 256; off <<= 1) {
        int t = (tid >= off) ? s[tid - off] : 0;
        __syncthreads();
        s[tid] += t;
        __syncthreads();
    }
    if (i < N_NODES) g_scan[i] = s[tid] - v;
    if (tid == 255) g_bsum[blockIdx.x] = s[255];
}

__global__ void scanB_kernel() {      // single block, 512 threads
    __shared__ int s[512];
    int tid = threadIdx.x;
    int v = (tid < NB_SCAN) ? g_bsum[tid] : 0;
    s[tid] = v;
    __syncthreads();
#pragma unroll
    for (int off = 1; off < 512; off <<= 1) {
        int t = (tid >= off) ? s[tid - off] : 0;
        __syncthreads();
        s[tid] += t;
        __syncthreads();
    }
    if (tid < NB_SCAN) g_boff[tid] = s[tid] - v;
}

__global__ void scanC_kernel() {
    int i = blockIdx.x * 256 + threadIdx.x;
    if (i < N_NODES) {
        int r = g_scan[i] + g_boff[blockIdx.x];
        g_rowstart[i] = r;
        g_cursor[i] = r;
    }
    if (i == 0) g_rowstart[N_NODES] = N_EDGES;
}

__global__ void csr_fill_kernel(const int* __restrict__ ei) {
    int e = blockIdx.x * blockDim.x + threadIdx.x;
    if (e >= N_EDGES) return;
    int s = ei[e];
    int d = ei[N_EDGES + e];
    float w = __ldg(g_dis + s) * __ldg(g_dis + d);
    int pos = atomicAdd(&g_cursor[d], 1);
    g_csr[pos] = make_int2(s, __float_as_int(w));
}

// ---------------- layer-1 agg: z16[n] = sum_in x16[src]*w + x16[n]*d2 -------
// one warp per destination node; lanes 0..15 hold the 32-col fp16 row (4B each)
__global__ __launch_bounds__(256)
void agg_x16_kernel() {
    int warp = threadIdx.x >> 5;
    int lane = threadIdx.x & 31;
    int n = blockIdx.x * 8 + warp;
    if (n >= N_NODES) return;

    int p0 = g_rowstart[n];
    int p1 = g_rowstart[n + 1];
    float d = g_dis[n];
    float d2 = d * d;

    unsigned hv = (lane < 16)
        ? __ldg((const unsigned*)(g_x16 + (size_t)n * K1PAD) + lane) : 0u;
    float2 h = __half22float2(*reinterpret_cast<__half2*>(&hv));
    float2 acc = make_float2(h.x * d2, h.y * d2);

#pragma unroll 8
    for (int p = p0; p < p1; p++) {
        int2 sw = __ldg(g_csr + p);
        float w = __int_as_float(sw.y);
        unsigned v = (lane < 16)
            ? __ldg((const unsigned*)(g_x16 + (size_t)sw.x * K1PAD) + lane) : 0u;
        float2 f = __half22float2(*reinterpret_cast<__half2*>(&v));
        acc.x += f.x * w;
        acc.y += f.y * w;
    }
    if (lane < 16) {
        __half2 o = __floats2half2_rn(acc.x, acc.y);
        ((unsigned*)(g_z16 + (size_t)n * K1PAD))[lane] =
            *reinterpret_cast<unsigned*>(&o);
    }
}

// ---------------- layer-1 tc GEMM: h16A = relu(z16 @ W1h + b1), K=32 --------
#define TCBM 64
__global__ __launch_bounds__(256, 2)
void gemm1_tc_kernel(const float* __restrict__ b) {
    __shared__ alignas(16) __half As[TCBM * K1PAD];   // 4 KB
    __shared__ alignas(16) __half Ws[K1PAD * HID];    // 8 KB
    __shared__ alignas(16) float stage[8 * 256];      // 8 KB

    int tid = threadIdx.x;
    int wid = tid >> 5;
    int lane = tid & 31;
    int rs = wid >> 1;
    int cs = wid & 1;
    int row0 = blockIdx.x * TCBM;

    for (int i = tid; i < TCBM * 4; i += 256) {
        int r = i >> 2;
        int c = i & 3;
        uint4 v = make_uint4(0u, 0u, 0u, 0u);
        int row = row0 + r;
        if (row < N_NODES)
            v = *reinterpret_cast<const uint4*>(g_z16 + (size_t)row * K1PAD + c * 8);
        *reinterpret_cast<uint4*>(As + r * K1PAD + c * 8) = v;
    }
    for (int i = tid; i < K1PAD * 16; i += 256) {
        int r = i >> 4;
        int c = i & 15;
        *reinterpret_cast<uint4*>(Ws + r * HID + c * 8) =
            *reinterpret_cast<const uint4*>(g_W1h + r * HID + c * 8);
    }
    __syncthreads();

    wmma::fragment<wmma::accumulator, 16, 16, 16, float> acc[4];
#pragma unroll
    for (int j = 0; j < 4; j++) wmma::fill_fragment(acc[j], 0.f);

#pragma unroll
    for (int k = 0; k < 2; k++) {
        wmma::fragment<wmma::matrix_a, 16, 16, 16, __half, wmma::row_major> af;
        wmma::load_matrix_sync(af, As + (rs * 16) * K1PAD + k * 16, K1PAD);
#pragma unroll
        for (int j = 0; j < 4; j++) {
            wmma::fragment<wmma::matrix_b, 16, 16, 16, __half, wmma::row_major> bf;
            wmma::load_matrix_sync(bf, Ws + (k * 16) * HID + cs * 64 + j * 16, HID);
            wmma::mma_sync(acc[j], af, bf, acc[j]);
        }
    }

    float* st = stage + wid * 256;
#pragma unroll
    for (int j = 0; j < 4; j++) {
        wmma::store_matrix_sync(st, acc[j], 16, wmma::mem_row_major);
        __syncwarp();
        int r = lane >> 1;
        int c0 = (lane & 1) * 8;
        int row = row0 + rs * 16 + r;
        if (row < N_NODES) {
            int col = cs * 64 + j * 16 + c0;
            float* sp = st + r * 16 + c0;
            float v[8];
#pragma unroll
            for (int q = 0; q < 8; q++) v[q] = fmaxf(sp[q] + __ldg(b + col + q), 0.f);
            __half2 h0 = __floats2half2_rn(v[0], v[1]);
            __half2 h1 = __floats2half2_rn(v[2], v[3]);
            __half2 h2 = __floats2half2_rn(v[4], v[5]);
            __half2 h3 = __floats2half2_rn(v[6], v[7]);
            uint4 u;
            u.x = *reinterpret_cast<unsigned*>(&h0);
            u.y = *reinterpret_cast<unsigned*>(&h1);
            u.z = *reinterpret_cast<unsigned*>(&h2);
            u.w = *reinterpret_cast<unsigned*>(&h3);
            *reinterpret_cast<uint4*>(g_h16A + (size_t)row * HID + col) = u;
        }
        __syncwarp();
    }
}

// ---------------- tensor-core GEMM (layers 2/3): g_hw16 = A16 @ W16 ---------
__global__ __launch_bounds__(256, 2)
void gemm_tc_kernel(const __half* __restrict__ A, const __half* __restrict__ W) {
    __shared__ alignas(16) __half As[TCBM * HID];   // 16 KB
    __shared__ alignas(16) __half Ws[64 * HID];     // 16 KB (reused as stage)

    int tid = threadIdx.x;
    int wid = tid >> 5;
    int lane = tid & 31;
    int rs = wid >> 1;
    int cs = wid & 1;
    int row0 = blockIdx.x * TCBM;

    for (int i = tid; i < TCBM * 16; i += 256) {
        int r = i >> 4;
        int c = i & 15;
        uint4 v = make_uint4(0u, 0u, 0u, 0u);
        int row = row0 + r;
        if (row < N_NODES)
            v = *reinterpret_cast<const uint4*>(A + (size_t)row * HID + c * 8);
        *reinterpret_cast<uint4*>(As + r * HID + c * 8) = v;
    }

    wmma::fragment<wmma::accumulator, 16, 16, 16, float> acc[4];
#pragma unroll
    for (int j = 0; j < 4; j++) wmma::fill_fragment(acc[j], 0.f);

#pragma unroll
    for (int ch = 0; ch < 2; ch++) {
        __syncthreads();
        for (int i = tid; i < 64 * 16; i += 256) {
            int r = i >> 4;
            int c = i & 15;
            *reinterpret_cast<uint4*>(Ws + r * HID + c * 8) =
                *reinterpret_cast<const uint4*>(W + (size_t)(ch * 64 + r) * HID + c * 8);
        }
        __syncthreads();
#pragma unroll
        for (int k = 0; k < 4; k++) {
            wmma::fragment<wmma::matrix_a, 16, 16, 16, __half, wmma::row_major> af;
            wmma::load_matrix_sync(af, As + (rs * 16) * HID + ch * 64 + k * 16, HID);
#pragma unroll
            for (int j = 0; j < 4; j++) {
                wmma::fragment<wmma::matrix_b, 16, 16, 16, __half, wmma::row_major> bf;
                wmma::load_matrix_sync(bf, Ws + (k * 16) * HID + cs * 64 + j * 16, HID);
                wmma::mma_sync(acc[j], af, bf, acc[j]);
            }
        }
    }
    __syncthreads();            // all mma done; Ws free for staging

    float* stage = reinterpret_cast<float*>(Ws) + wid * 256;
#pragma unroll
    for (int j = 0; j < 4; j++) {
        wmma::store_matrix_sync(stage, acc[j], 16, wmma::mem_row_major);
        __syncwarp();
        int r = lane >> 1;
        int c0 = (lane & 1) * 8;
        int row = row0 + rs * 16 + r;
        if (row < N_NODES) {
            float* sp = stage + r * 16 + c0;
            __half2 h0 = __floats2half2_rn(sp[0], sp[1]);
            __half2 h1 = __floats2half2_rn(sp[2], sp[3]);
            __half2 h2 = __floats2half2_rn(sp[4], sp[5]);
            __half2 h3 = __floats2half2_rn(sp[6], sp[7]);
            uint4 u;
            u.x = *reinterpret_cast<unsigned*>(&h0);
            u.y = *reinterpret_cast<unsigned*>(&h1);
            u.z = *reinterpret_cast<unsigned*>(&h2);
            u.w = *reinterpret_cast<unsigned*>(&h3);
            *reinterpret_cast<uint4*>(g_hw16 + (size_t)row * HID + cs * 64 + j * 16 + c0) = u;
        }
        __syncwarp();
    }
}

// ---------------- CSR agg: out16 = relu( sum hw16[src]*w + hw16[n]*d2 + b ) -
__global__ __launch_bounds__(256)
void agg_h16_kernel(const float* __restrict__ b, __half* __restrict__ out) {
    int warp = threadIdx.x >> 5;
    int lane = threadIdx.x & 31;
    int n = blockIdx.x * 8 + warp;
    if (n >= N_NODES) return;

    int p0 = g_rowstart[n];
    int p1 = g_rowstart[n + 1];

    float d = g_dis[n];
    float d2 = d * d;
    uint2 hr = __ldg((const uint2*)(g_hw16 + (size_t)n * HID) + lane);
    float2 h01 = __half22float2(*reinterpret_cast<__half2*>(&hr.x));
    float2 h23 = __half22float2(*reinterpret_cast<__half2*>(&hr.y));
    float4 bv = __ldg((const float4*)b + lane);
    float4 a = make_float4(h01.x * d2 + bv.x, h01.y * d2 + bv.y,
                           h23.x * d2 + bv.z, h23.y * d2 + bv.w);

#pragma unroll 8
    for (int p = p0; p < p1; p++) {
        int2 sw = __ldg(g_csr + p);
        float w = __int_as_float(sw.y);
        uint2 vr = __ldg((const uint2*)(g_hw16 + (size_t)sw.x * HID) + lane);
        float2 v01 = __half22float2(*reinterpret_cast<__half2*>(&vr.x));
        float2 v23 = __half22float2(*reinterpret_cast<__half2*>(&vr.y));
        a.x += v01.x * w;
        a.y += v01.y * w;
        a.z += v23.x * w;
        a.w += v23.y * w;
    }
    a.x = fmaxf(a.x, 0.f);
    a.y = fmaxf(a.y, 0.f);
    a.z = fmaxf(a.z, 0.f);
    a.w = fmaxf(a.w, 0.f);
    __half2 o0 = __floats2half2_rn(a.x, a.y);
    __half2 o1 = __floats2half2_rn(a.z, a.w);
    uint2 u;
    u.x = *reinterpret_cast<unsigned*>(&o0);
    u.y = *reinterpret_cast<unsigned*>(&o1);
    ((uint2*)(out + (size_t)n * HID))[lane] = u;
}

// ---------------- pooling (input already relu'd fp16) ------------------------
__global__ __launch_bounds__(128)
void pool_kernel(const __half* __restrict__ h, const int* __restrict__ batch) {
    int c = threadIdx.x;
    int n0 = blockIdx.x * 128;
    int nend = min(n0 + 128, N_NODES);
    if (n0 >= nend) return;
    int curg = batch[n0];
    float run = 0.f;
    int rl = 0;
    for (int n = n0; n < nend; n++) {
        int g = batch[n];
        if (g != curg) {
            atomicAdd(&g_pool[curg * HID + c], run);
            if (c == 0) atomicAdd(&g_cnt[curg], (float)rl);
            run = 0.f; rl = 0; curg = g;
        }
        run += __half2float(h[(size_t)n * HID + c]);
        rl++;
    }
    atomicAdd(&g_pool[curg * HID + c], run);
    if (c == 0) atomicAdd(&g_cnt[curg], (float)rl);
}

// ---------------- heads -----------------------------------------------------
__global__ __launch_bounds__(256)
void head_kernel(const float* __restrict__ Wmu, const float* __restrict__ bmu,
                 const float* __restrict__ Wlv, const float* __restrict__ blv,
                 float* __restrict__ out) {
    __shared__ float p[HID];
    int g = blockIdx.x;
    int j = threadIdx.x;
    if (j < HID) {
        float c = fmaxf(g_cnt[g], 1.f);
        p[j] = g_pool[g * HID + j] / c;
    }
    __syncthreads();
    float smu = bmu[j];
    float slv = blv[j];
#pragma unroll 4
    for (int k = 0; k < HID; k++) {
        float pk = p[k];
        smu += pk * Wmu[k * LAT + j];
        slv += pk * Wlv[k * LAT + j];
    }
    out[(size_t)g * LAT + j] = smu;
    out[(size_t)N_GRAPHS * LAT + (size_t)g * LAT + j] = slv;
}

// ---------------- launch ----------------------------------------------------
extern "C" void kernel_launch(void* const* d_in, const int* in_sizes, int n_in,
                              void* d_out, int out_size) {
    const float* x     = (const float*)d_in[0];
    const int*   ei    = (const int*)d_in[1];
    const int*   batch = (const int*)d_in[2];
    const float* W1  = (const float*)d_in[3];
    const float* b1  = (const float*)d_in[4];
    const float* W2  = (const float*)d_in[5];
    const float* b2  = (const float*)d_in[6];
    const float* W3  = (const float*)d_in[7];
    const float* b3  = (const float*)d_in[8];
    const float* Wmu = (const float*)d_in[9];
    const float* bmu = (const float*)d_in[10];
    const float* Wlv = (const float*)d_in[11];
    const float* blv = (const float*)d_in[12];
    float* out = (float*)d_out;

    __half *pA16, *pB16, *pW2h, *pW3h;
    cudaGetSymbolAddress((void**)&pA16, g_h16A);
    cudaGetSymbolAddress((void**)&pB16, g_h16B);
    cudaGetSymbolAddress((void**)&pW2h, g_W2h);
    cudaGetSymbolAddress((void**)&pW3h, g_W3h);

    int nb_edges = (N_EDGES + 255) / 256;

    prep_kernel<<<(N_NODES * K1PAD + 255) / 256, 256>>>(x, W1, W2, W3);
    edge_count_kernel<<<nb_edges, 256>>>(ei);
    scanA_kernel<<<NB_SCAN, 256>>>();
    scanB_kernel<<<1, 512>>>();
    scanC_kernel<<<NB_SCAN, 256>>>();
    csr_fill_kernel<<<nb_edges, 256>>>(ei);

    int nb_gtc = (N_NODES + TCBM - 1) / TCBM;
    int nb_agg = (N_NODES + 7) / 8;

    // layer 1 (reordered): z16 = agg(x16) ; h16A = relu(z16 @ W1 + b1)
    agg_x16_kernel<<<nb_agg, 256>>>();
    gemm1_tc_kernel<<<nb_gtc, 256>>>(b1);
    // layer 2: hw16 = h16A @ W2 ; h16B = relu(agg(hw16) + b2)
    gemm_tc_kernel<<<nb_gtc, 256>>>(pA16, pW2h);
    agg_h16_kernel<<<nb_agg, 256>>>(b2, pB16);
    // layer 3: hw16 = h16B @ W3 ; h16A = relu(agg(hw16) + b3)
    gemm_tc_kernel<<<nb_gtc, 256>>>(pB16, pW3h);
    agg_h16_kernel<<<nb_agg, 256>>>(b3, pA16);

    pool_kernel<<<(N_NODES + 127) / 128, 128>>>(pA16, batch);
    head_kernel<<<N_GRAPHS, 256>>>(Wmu, bmu, Wlv, blv, out);
}

// round 14
// speedup vs baseline: 1.0755x; 1.0381x over previous
#include <cuda_runtime.h>
#include <cuda_bf16.h>
#include <cuda_fp16.h>
#include <mma.h>
#include <cstdint>

using namespace nvcuda;

#define N_NODES 100000
#define N_EDGES 3200000
#define N_GRAPHS 512
#define IN_DIM 29
#define K1PAD 32
#define HID 128
#define LAT 256
#define NB_SCAN ((N_NODES + 255) / 256)   // 391

// ---------------- scratch (static device globals; no allocation) -----------
__device__ __half g_hw16[(size_t)N_NODES * HID];  // gemm output (pre-bias)
__device__ __half g_h16A[(size_t)N_NODES * HID];  // relu'd layer act ping
__device__ __half g_h16B[(size_t)N_NODES * HID];  // relu'd layer act pong
__device__ __half g_x16[(size_t)N_NODES * K1PAD]; // fp16 x, padded to 32
__device__ __half g_z16[(size_t)N_NODES * K1PAD]; // aggregated x (fp16)
__device__ __half g_W1h[K1PAD * HID];             // padded fp16 W1
__device__ __half g_W2h[HID * HID];
__device__ __half g_W3h[HID * HID];
__device__ float g_dis[N_NODES];                  // deg^-1/2 (with self loop)
__device__ int   g_deg[N_NODES];
__device__ int   g_scan[N_NODES];
__device__ int   g_bsum[NB_SCAN];
__device__ int   g_boff[NB_SCAN];
__device__ int   g_rowstart[N_NODES + 1];         // CSR row offsets (by dst)
__device__ int   g_cursor[N_NODES];
__device__ int2  g_csr[N_EDGES];                  // (src, bitcast(weight))
__device__ float g_pool[N_GRAPHS * HID];
__device__ float g_cnt[N_GRAPHS];

// ---------------- zero accumulators (feeds edge_count; default stream) ------
__global__ void zero_kernel() {
    int i = blockIdx.x * blockDim.x + threadIdx.x;
    if (i < N_NODES) g_deg[i] = 0;
    if (i < N_GRAPHS * HID) g_pool[i] = 0.f;
    if (i < N_GRAPHS) g_cnt[i] = 0.f;
}

// ---------------- fp16 conversions (independent; side stream) ---------------
__global__ void conv16_kernel(const float* __restrict__ x,
                              const float* __restrict__ W1,
                              const float* __restrict__ W2,
                              const float* __restrict__ W3) {
    int i = blockIdx.x * blockDim.x + threadIdx.x;
    if (i < N_NODES * K1PAD) {
        int n = i >> 5;
        int c = i & 31;
        g_x16[i] = (c < IN_DIM) ? __float2half(x[(size_t)n * IN_DIM + c]) : __half(0.f);
    }
    if (i < HID * HID) {
        g_W2h[i] = __float2half(W2[i]);
        g_W3h[i] = __float2half(W3[i]);
    }
    if (i < K1PAD * HID) {
        int k = i >> 7;
        g_W1h[i] = (k < IN_DIM) ? __float2half(W1[i]) : __half(0.f);
    }
}

// ---------------- edge prep ------------------------------------------------
__global__ void edge_count_kernel(const int* __restrict__ ei) {
    int e = blockIdx.x * blockDim.x + threadIdx.x;
    if (e >= N_EDGES) return;
    atomicAdd(&g_deg[ei[N_EDGES + e]], 1);
}

// ---------------- CSR build: 3-pass scan + fill (dis fused into scanA) ------
__global__ void scanA_kernel() {
    __shared__ int s[256];
    int tid = threadIdx.x;
    int i = blockIdx.x * 256 + tid;
    int v = (i < N_NODES) ? g_deg[i] : 0;
    if (i < N_NODES) g_dis[i] = rsqrtf((float)(v + 1));
    s[tid] = v;
    __syncthreads();
#pragma unroll
    for (int off = 1; off < 256; off <<= 1) {
        int t = (tid >= off) ? s[tid - off] : 0;
        __syncthreads();
        s[tid] += t;
        __syncthreads();
    }
    if (i < N_NODES) g_scan[i] = s[tid] - v;
    if (tid == 255) g_bsum[blockIdx.x] = s[255];
}

__global__ void scanB_kernel() {      // single block, 512 threads
    __shared__ int s[512];
    int tid = threadIdx.x;
    int v = (tid < NB_SCAN) ? g_bsum[tid] : 0;
    s[tid] = v;
    __syncthreads();
#pragma unroll
    for (int off = 1; off < 512; off <<= 1) {
        int t = (tid >= off) ? s[tid - off] : 0;
        __syncthreads();
        s[tid] += t;
        __syncthreads();
    }
    if (tid < NB_SCAN) g_boff[tid] = s[tid] - v;
}

__global__ void scanC_kernel() {
    int i = blockIdx.x * 256 + threadIdx.x;
    if (i < N_NODES) {
        int r = g_scan[i] + g_boff[blockIdx.x];
        g_rowstart[i] = r;
        g_cursor[i] = r;
    }
    if (i == 0) g_rowstart[N_NODES] = N_EDGES;
}

__global__ void csr_fill_kernel(const int* __restrict__ ei) {
    int e = blockIdx.x * blockDim.x + threadIdx.x;
    if (e >= N_EDGES) return;
    int s = ei[e];
    int d = ei[N_EDGES + e];
    float w = __ldg(g_dis + s) * __ldg(g_dis + d);
    int pos = atomicAdd(&g_cursor[d], 1);
    g_csr[pos] = make_int2(s, __float_as_int(w));
}

// ---------------- layer-1 agg: z16[n] = sum_in x16[src]*w + x16[n]*d2 -------
// TWO nodes per warp: lanes 0..15 -> node A, lanes 16..31 -> node B.
__global__ __launch_bounds__(256)
void agg_x16_kernel() {
    int warp = threadIdx.x >> 5;
    int half = (threadIdx.x >> 4) & 1;
    int lane16 = threadIdx.x & 15;
    int n = blockIdx.x * 16 + warp * 2 + half;
    if (n >= N_NODES) return;

    int p0 = g_rowstart[n];
    int p1 = g_rowstart[n + 1];
    float d = g_dis[n];
    float d2 = d * d;

    unsigned hv = __ldg((const unsigned*)(g_x16 + (size_t)n * K1PAD) + lane16);
    float2 h = __half22float2(*reinterpret_cast<__half2*>(&hv));
    float2 acc = make_float2(h.x * d2, h.y * d2);

#pragma unroll 8
    for (int p = p0; p < p1; p++) {
        int2 sw = __ldg(g_csr + p);
        float w = __int_as_float(sw.y);
        unsigned v = __ldg((const unsigned*)(g_x16 + (size_t)sw.x * K1PAD) + lane16);
        float2 f = __half22float2(*reinterpret_cast<__half2*>(&v));
        acc.x += f.x * w;
        acc.y += f.y * w;
    }
    __half2 o = __floats2half2_rn(acc.x, acc.y);
    ((unsigned*)(g_z16 + (size_t)n * K1PAD))[lane16] =
        *reinterpret_cast<unsigned*>(&o);
}

// ---------------- layer-1 tc GEMM: h16A = relu(z16 @ W1h + b1), K=32 --------
#define TCBM 64
__global__ __launch_bounds__(256, 2)
void gemm1_tc_kernel(const float* __restrict__ b) {
    __shared__ alignas(16) __half As[TCBM * K1PAD];   // 4 KB
    __shared__ alignas(16) __half Ws[K1PAD * HID];    // 8 KB
    __shared__ alignas(16) float stage[8 * 256];      // 8 KB

    int tid = threadIdx.x;
    int wid = tid >> 5;
    int lane = tid & 31;
    int rs = wid >> 1;
    int cs = wid & 1;
    int row0 = blockIdx.x * TCBM;

    for (int i = tid; i < TCBM * 4; i += 256) {
        int r = i >> 2;
        int c = i & 3;
        uint4 v = make_uint4(0u, 0u, 0u, 0u);
        int row = row0 + r;
        if (row < N_NODES)
            v = *reinterpret_cast<const uint4*>(g_z16 + (size_t)row * K1PAD + c * 8);
        *reinterpret_cast<uint4*>(As + r * K1PAD + c * 8) = v;
    }
    for (int i = tid; i < K1PAD * 16; i += 256) {
        int r = i >> 4;
        int c = i & 15;
        *reinterpret_cast<uint4*>(Ws + r * HID + c * 8) =
            *reinterpret_cast<const uint4*>(g_W1h + r * HID + c * 8);
    }
    __syncthreads();

    wmma::fragment<wmma::accumulator, 16, 16, 16, float> acc[4];
#pragma unroll
    for (int j = 0; j < 4; j++) wmma::fill_fragment(acc[j], 0.f);

#pragma unroll
    for (int k = 0; k < 2; k++) {
        wmma::fragment<wmma::matrix_a, 16, 16, 16, __half, wmma::row_major> af;
        wmma::load_matrix_sync(af, As + (rs * 16) * K1PAD + k * 16, K1PAD);
#pragma unroll
        for (int j = 0; j < 4; j++) {
            wmma::fragment<wmma::matrix_b, 16, 16, 16, __half, wmma::row_major> bf;
            wmma::load_matrix_sync(bf, Ws + (k * 16) * HID + cs * 64 + j * 16, HID);
            wmma::mma_sync(acc[j], af, bf, acc[j]);
        }
    }

    float* st = stage + wid * 256;
#pragma unroll
    for (int j = 0; j < 4; j++) {
        wmma::store_matrix_sync(st, acc[j], 16, wmma::mem_row_major);
        __syncwarp();
        int r = lane >> 1;
        int c0 = (lane & 1) * 8;
        int row = row0 + rs * 16 + r;
        if (row < N_NODES) {
            int col = cs * 64 + j * 16 + c0;
            float* sp = st + r * 16 + c0;
            float v[8];
#pragma unroll
            for (int q = 0; q < 8; q++) v[q] = fmaxf(sp[q] + __ldg(b + col + q), 0.f);
            __half2 h0 = __floats2half2_rn(v[0], v[1]);
            __half2 h1 = __floats2half2_rn(v[2], v[3]);
            __half2 h2 = __floats2half2_rn(v[4], v[5]);
            __half2 h3 = __floats2half2_rn(v[6], v[7]);
            uint4 u;
            u.x = *reinterpret_cast<unsigned*>(&h0);
            u.y = *reinterpret_cast<unsigned*>(&h1);
            u.z = *reinterpret_cast<unsigned*>(&h2);
            u.w = *reinterpret_cast<unsigned*>(&h3);
            *reinterpret_cast<uint4*>(g_h16A + (size_t)row * HID + col) = u;
        }
        __syncwarp();
    }
}

// ---------------- tensor-core GEMM (layers 2/3): g_hw16 = A16 @ W16 ---------
__global__ __launch_bounds__(256, 2)
void gemm_tc_kernel(const __half* __restrict__ A, const __half* __restrict__ W) {
    __shared__ alignas(16) __half As[TCBM * HID];   // 16 KB
    __shared__ alignas(16) __half Ws[64 * HID];     // 16 KB (reused as stage)

    int tid = threadIdx.x;
    int wid = tid >> 5;
    int lane = tid & 31;
    int rs = wid >> 1;
    int cs = wid & 1;
    int row0 = blockIdx.x * TCBM;

    for (int i = tid; i < TCBM * 16; i += 256) {
        int r = i >> 4;
        int c = i & 15;
        uint4 v = make_uint4(0u, 0u, 0u, 0u);
        int row = row0 + r;
        if (row < N_NODES)
            v = *reinterpret_cast<const uint4*>(A + (size_t)row * HID + c * 8);
        *reinterpret_cast<uint4*>(As + r * HID + c * 8) = v;
    }

    wmma::fragment<wmma::accumulator, 16, 16, 16, float> acc[4];
#pragma unroll
    for (int j = 0; j < 4; j++) wmma::fill_fragment(acc[j], 0.f);

#pragma unroll
    for (int ch = 0; ch < 2; ch++) {
        __syncthreads();
        for (int i = tid; i < 64 * 16; i += 256) {
            int r = i >> 4;
            int c = i & 15;
            *reinterpret_cast<uint4*>(Ws + r * HID + c * 8) =
                *reinterpret_cast<const uint4*>(W + (size_t)(ch * 64 + r) * HID + c * 8);
        }
        __syncthreads();
#pragma unroll
        for (int k = 0; k < 4; k++) {
            wmma::fragment<wmma::matrix_a, 16, 16, 16, __half, wmma::row_major> af;
            wmma::load_matrix_sync(af, As + (rs * 16) * HID + ch * 64 + k * 16, HID);
#pragma unroll
            for (int j = 0; j < 4; j++) {
                wmma::fragment<wmma::matrix_b, 16, 16, 16, __half, wmma::row_major> bf;
                wmma::load_matrix_sync(bf, Ws + (k * 16) * HID + cs * 64 + j * 16, HID);
                wmma::mma_sync(acc[j], af, bf, acc[j]);
            }
        }
    }
    __syncthreads();            // all mma done; Ws free for staging

    float* stage = reinterpret_cast<float*>(Ws) + wid * 256;
#pragma unroll
    for (int j = 0; j < 4; j++) {
        wmma::store_matrix_sync(stage, acc[j], 16, wmma::mem_row_major);
        __syncwarp();
        int r = lane >> 1;
        int c0 = (lane & 1) * 8;
        int row = row0 + rs * 16 + r;
        if (row < N_NODES) {
            float* sp = stage + r * 16 + c0;
            __half2 h0 = __floats2half2_rn(sp[0], sp[1]);
            __half2 h1 = __floats2half2_rn(sp[2], sp[3]);
            __half2 h2 = __floats2half2_rn(sp[4], sp[5]);
            __half2 h3 = __floats2half2_rn(sp[6], sp[7]);
            uint4 u;
            u.x = *reinterpret_cast<unsigned*>(&h0);
            u.y = *reinterpret_cast<unsigned*>(&h1);
            u.z = *reinterpret_cast<unsigned*>(&h2);
            u.w = *reinterpret_cast<unsigned*>(&h3);
            *reinterpret_cast<uint4*>(g_hw16 + (size_t)row * HID + cs * 64 + j * 16 + c0) = u;
        }
        __syncwarp();
    }
}

// ---------------- CSR agg: out16 = relu( sum hw16[src]*w + hw16[n]*d2 + b ) -
__global__ __launch_bounds__(256)
void agg_h16_kernel(const float* __restrict__ b, __half* __restrict__ out) {
    int warp = threadIdx.x >> 5;
    int lane = threadIdx.x & 31;
    int n = blockIdx.x * 8 + warp;
    if (n >= N_NODES) return;

    int p0 = g_rowstart[n];
    int p1 = g_rowstart[n + 1];

    float d = g_dis[n];
    float d2 = d * d;
    uint2 hr = __ldg((const uint2*)(g_hw16 + (size_t)n * HID) + lane);
    float2 h01 = __half22float2(*reinterpret_cast<__half2*>(&hr.x));
    float2 h23 = __half22float2(*reinterpret_cast<__half2*>(&hr.y));
    float4 bv = __ldg((const float4*)b + lane);
    float4 a = make_float4(h01.x * d2 + bv.x, h01.y * d2 + bv.y,
                           h23.x * d2 + bv.z, h23.y * d2 + bv.w);

#pragma unroll 8
    for (int p = p0; p < p1; p++) {
        int2 sw = __ldg(g_csr + p);
        float w = __int_as_float(sw.y);
        uint2 vr = __ldg((const uint2*)(g_hw16 + (size_t)sw.x * HID) + lane);
        float2 v01 = __half22float2(*reinterpret_cast<__half2*>(&vr.x));
        float2 v23 = __half22float2(*reinterpret_cast<__half2*>(&vr.y));
        a.x += v01.x * w;
        a.y += v01.y * w;
        a.z += v23.x * w;
        a.w += v23.y * w;
    }
    a.x = fmaxf(a.x, 0.f);
    a.y = fmaxf(a.y, 0.f);
    a.z = fmaxf(a.z, 0.f);
    a.w = fmaxf(a.w, 0.f);
    __half2 o0 = __floats2half2_rn(a.x, a.y);
    __half2 o1 = __floats2half2_rn(a.z, a.w);
    uint2 u;
    u.x = *reinterpret_cast<unsigned*>(&o0);
    u.y = *reinterpret_cast<unsigned*>(&o1);
    ((uint2*)(out + (size_t)n * HID))[lane] = u;
}

// ---------------- pooling (input already relu'd fp16) ------------------------
__global__ __launch_bounds__(128)
void pool_kernel(const __half* __restrict__ h, const int* __restrict__ batch) {
    int c = threadIdx.x;
    int n0 = blockIdx.x * 128;
    int nend = min(n0 + 128, N_NODES);
    if (n0 >= nend) return;
    int curg = batch[n0];
    float run = 0.f;
    int rl = 0;
    for (int n = n0; n < nend; n++) {
        int g = batch[n];
        if (g != curg) {
            atomicAdd(&g_pool[curg * HID + c], run);
            if (c == 0) atomicAdd(&g_cnt[curg], (float)rl);
            run = 0.f; rl = 0; curg = g;
        }
        run += __half2float(h[(size_t)n * HID + c]);
        rl++;
    }
    atomicAdd(&g_pool[curg * HID + c], run);
    if (c == 0) atomicAdd(&g_cnt[curg], (float)rl);
}

// ---------------- heads -----------------------------------------------------
__global__ __launch_bounds__(256)
void head_kernel(const float* __restrict__ Wmu, const float* __restrict__ bmu,
                 const float* __restrict__ Wlv, const float* __restrict__ blv,
                 float* __restrict__ out) {
    __shared__ float p[HID];
    int g = blockIdx.x;
    int j = threadIdx.x;
    if (j < HID) {
        float c = fmaxf(g_cnt[g], 1.f);
        p[j] = g_pool[g * HID + j] / c;
    }
    __syncthreads();
    float smu = bmu[j];
    float slv = blv[j];
#pragma unroll 4
    for (int k = 0; k < HID; k++) {
        float pk = p[k];
        smu += pk * Wmu[k * LAT + j];
        slv += pk * Wlv[k * LAT + j];
    }
    out[(size_t)g * LAT + j] = smu;
    out[(size_t)N_GRAPHS * LAT + (size_t)g * LAT + j] = slv;
}

// ---------------- launch ----------------------------------------------------
extern "C" void kernel_launch(void* const* d_in, const int* in_sizes, int n_in,
                              void* d_out, int out_size) {
    const float* x     = (const float*)d_in[0];
    const int*   ei    = (const int*)d_in[1];
    const int*   batch = (const int*)d_in[2];
    const float* W1  = (const float*)d_in[3];
    const float* b1  = (const float*)d_in[4];
    const float* W2  = (const float*)d_in[5];
    const float* b2  = (const float*)d_in[6];
    const float* W3  = (const float*)d_in[7];
    const float* b3  = (const float*)d_in[8];
    const float* Wmu = (const float*)d_in[9];
    const float* bmu = (const float*)d_in[10];
    const float* Wlv = (const float*)d_in[11];
    const float* blv = (const float*)d_in[12];
    float* out = (float*)d_out;

    __half *pA16, *pB16, *pW2h, *pW3h;
    cudaGetSymbolAddress((void**)&pA16, g_h16A);
    cudaGetSymbolAddress((void**)&pB16, g_h16B);
    cudaGetSymbolAddress((void**)&pW2h, g_W2h);
    cudaGetSymbolAddress((void**)&pW3h, g_W3h);

    int nb_edges = (N_EDGES + 255) / 256;
    int nb_nodes = (N_NODES + 255) / 256;

    // fork: fp16 conversions run on a side stream, overlapped with the
    // edge pipeline (zero -> count -> scans -> fill) on the main stream.
    cudaStream_t s2;
    cudaStreamCreateWithFlags(&s2, cudaStreamNonBlocking);
    cudaEvent_t evFork, evJoin;
    cudaEventCreateWithFlags(&evFork, cudaEventDisableTiming);
    cudaEventCreateWithFlags(&evJoin, cudaEventDisableTiming);

    cudaEventRecord(evFork, 0);
    cudaStreamWaitEvent(s2, evFork, 0);
    conv16_kernel<<<(N_NODES * K1PAD + 255) / 256, 256, 0, s2>>>(x, W1, W2, W3);
    cudaEventRecord(evJoin, s2);

    zero_kernel<<<nb_nodes, 256>>>();
    edge_count_kernel<<<nb_edges, 256>>>(ei);
    scanA_kernel<<<NB_SCAN, 256>>>();
    scanB_kernel<<<1, 512>>>();
    scanC_kernel<<<NB_SCAN, 256>>>();
    csr_fill_kernel<<<nb_edges, 256>>>(ei);

    // join: agg_x16 needs x16 (side stream) + csr (main stream)
    cudaStreamWaitEvent(0, evJoin, 0);

    int nb_gtc = (N_NODES + TCBM - 1) / TCBM;
    int nb_agg = (N_NODES + 7) / 8;
    int nb_agg2 = (N_NODES + 15) / 16;

    // layer 1 (reordered): z16 = agg(x16) ; h16A = relu(z16 @ W1 + b1)
    agg_x16_kernel<<<nb_agg2, 256>>>();
    gemm1_tc_kernel<<<nb_gtc, 256>>>(b1);
    // layer 2: hw16 = h16A @ W2 ; h16B = relu(agg(hw16) + b2)
    gemm_tc_kernel<<<nb_gtc, 256>>>(pA16, pW2h);
    agg_h16_kernel<<<nb_agg, 256>>>(b2, pB16);
    // layer 3: hw16 = h16B @ W3 ; h16A = relu(agg(hw16) + b3)
    gemm_tc_kernel<<<nb_gtc, 256>>>(pB16, pW3h);
    agg_h16_kernel<<<nb_agg, 256>>>(b3, pA16);

    pool_kernel<<<(N_NODES + 127) / 128, 128>>>(pA16, batch);
    head_kernel<<<N_GRAPHS, 256>>>(Wmu, bmu, Wlv, blv, out);

    cudaEventDestroy(evFork);
    cudaEventDestroy(evJoin);
    cudaStreamDestroy(s2);
}